// round 16
// baseline (speedup 1.0000x reference)
#include <cuda_runtime.h>
#include <cuda_fp16.h>

namespace {
constexpr int NTOK = 4096;
constexpr int CDIM = 256;
constexpr int NSPLIT = 4;
constexpr int KEYS_PER_SPLIT = NTOK / NSPLIT;               // 1024
constexpr int ITERS = KEYS_PER_SPLIT / 64;                  // 16
constexpr int TQ = 128;                                     // queries per block
constexpr int ATT_SMEM  = (64 * 136 + 4 * 64 * 72) * 2;     // Q + 2K + 2V = 54272 B
constexpr int GEMM_SMEM = (2 * 64 * 56 + 2 * 32 * 136) * 2; // 31744 B
}

// Scratch (allocation-free rule: __device__ globals)
__device__ __half g_xn[CDIM * NTOK];
__device__ __half g_qkv[3 * CDIM * NTOK];
__device__ __half g_h[CDIM * NTOK];
__device__ __half g_wq[3 * CDIM * CDIM];
__device__ __half g_wp[CDIM * CDIM];
__device__ float2 g_part[128];
__device__ __half g_oparth[NSPLIT * CDIM * NTOK];  // fp16 partial O (unnormalized)
__device__ float  g_l[NSPLIT * 4 * NTOK];          // per (split, head, token) l-sum
__device__ float  g_linv[4 * NTOK];                // 1 / sum_s l_s per (head, token)

__device__ __forceinline__ unsigned saddr(const void* p) {
    return (unsigned)__cvta_generic_to_shared(p);
}
__device__ __forceinline__ void cpa16(unsigned dst, const void* src) {
    asm volatile("cp.async.cg.shared.global [%0], [%1], 16;\n" :: "r"(dst), "l"(src));
}
#define CP_COMMIT() asm volatile("cp.async.commit_group;\n" ::)
#define CP_WAIT0()  asm volatile("cp.async.wait_group 0;\n" ::)
#define CP_WAIT1()  asm volatile("cp.async.wait_group 1;\n" ::)

__device__ __forceinline__ unsigned h2u(__half2 h) {
    return *reinterpret_cast<unsigned*>(&h);
}
__device__ __forceinline__ unsigned ex2h2(unsigned x) {
    unsigned y;
    asm("ex2.approx.f16x2 %0, %1;" : "=r"(y) : "r"(x));
    return y;
}
__device__ __forceinline__ void mma16(float* c, const unsigned* a, unsigned b0, unsigned b1) {
    asm volatile(
        "mma.sync.aligned.m16n8k16.row.col.f32.f16.f16.f32 "
        "{%0,%1,%2,%3},{%4,%5,%6,%7},{%8,%9},{%0,%1,%2,%3};\n"
        : "+f"(c[0]), "+f"(c[1]), "+f"(c[2]), "+f"(c[3])
        : "r"(a[0]), "r"(a[1]), "r"(a[2]), "r"(a[3]), "r"(b0), "r"(b1));
}
__device__ __forceinline__ void ldm4(unsigned* r, unsigned a) {
    asm volatile("ldmatrix.sync.aligned.m8n8.x4.shared.b16 {%0,%1,%2,%3}, [%4];\n"
        : "=r"(r[0]), "=r"(r[1]), "=r"(r[2]), "=r"(r[3]) : "r"(a));
}
__device__ __forceinline__ void ldm4t(unsigned* r, unsigned a) {
    asm volatile("ldmatrix.sync.aligned.m8n8.x4.trans.shared.b16 {%0,%1,%2,%3}, [%4];\n"
        : "=r"(r[0]), "=r"(r[1]), "=r"(r[2]), "=r"(r[3]) : "r"(a));
}

// ---------------------------------------------------------------------------
// Fused: GN partial sums (blocks 0..127) + weight fp32->fp16 cvt (128..255)
// ---------------------------------------------------------------------------
__global__ __launch_bounds__(256) void gn_stats_cvt(
    const float* __restrict__ x,
    const float* __restrict__ wq, const float* __restrict__ wp,
    __half* __restrict__ dq, __half* __restrict__ dp)
{
    if (blockIdx.x < 128) {
        const int b = blockIdx.x;               // g*8 + slice
        const float4* xg = reinterpret_cast<const float4*>(x) + (size_t)b * 2048;
        float s = 0.f, s2 = 0.f;
        for (int i = threadIdx.x; i < 2048; i += 256) {
            float4 v = xg[i];
            s  += v.x + v.y + v.z + v.w;
            s2 += v.x * v.x + v.y * v.y + v.z * v.z + v.w * v.w;
        }
        #pragma unroll
        for (int o = 16; o; o >>= 1) {
            s  += __shfl_xor_sync(0xffffffffu, s, o);
            s2 += __shfl_xor_sync(0xffffffffu, s2, o);
        }
        __shared__ float r1[8], r2[8];
        if ((threadIdx.x & 31) == 0) { r1[threadIdx.x >> 5] = s; r2[threadIdx.x >> 5] = s2; }
        __syncthreads();
        if (threadIdx.x == 0) {
            float ts = 0.f, ts2 = 0.f;
            #pragma unroll
            for (int i = 0; i < 8; i++) { ts += r1[i]; ts2 += r2[i]; }
            g_part[b] = make_float2(ts, ts2);
        }
    } else {
        const int n1 = 3 * CDIM * CDIM / 2;
        const int nt = n1 + CDIM * CDIM / 2;
        for (int i = (blockIdx.x - 128) * 256 + threadIdx.x; i < nt; i += 128 * 256) {
            if (i < n1) {
                float2 v = reinterpret_cast<const float2*>(wq)[i];
                reinterpret_cast<__half2*>(dq)[i] = __floats2half2_rn(v.x, v.y);
            } else {
                float2 v = reinterpret_cast<const float2*>(wp)[i - n1];
                reinterpret_cast<__half2*>(dp)[i - n1] = __floats2half2_rn(v.x, v.y);
            }
        }
    }
}

// ---------------------------------------------------------------------------
// GroupNorm apply with inline per-channel scale computation, write fp16
// ---------------------------------------------------------------------------
__global__ __launch_bounds__(256) void gn_apply(
    const float* __restrict__ x, const float* __restrict__ gamma,
    const float* __restrict__ beta, __half* __restrict__ xn)
{
    __shared__ float2 sgab[CDIM];
    {
        const int c = threadIdx.x;
        const int g = c >> 4;
        float ts = 0.f, ts2 = 0.f;
        #pragma unroll
        for (int j = 0; j < 8; j++) { float2 p = g_part[g * 8 + j]; ts += p.x; ts2 += p.y; }
        const float inv = 1.f / 65536.f;
        float mu = ts * inv;
        float rstd = rsqrtf(ts2 * inv - mu * mu + 1e-5f);
        float ga = gamma[c] * rstd;
        sgab[c] = make_float2(ga, beta[c] - mu * ga);
    }
    __syncthreads();
    for (int i = blockIdx.x * 256 + threadIdx.x; i < 262144; i += gridDim.x * 256) {
        float2 gb = sgab[i >> 10];
        float4 v = reinterpret_cast<const float4*>(x)[i];
        uint2 o;
        o.x = h2u(__floats2half2_rn(v.x * gb.x + gb.y, v.y * gb.x + gb.y));
        o.y = h2u(__floats2half2_rn(v.z * gb.x + gb.y, v.w * gb.x + gb.y));
        reinterpret_cast<uint2*>(xn)[i] = o;
    }
}

// ---------------------------------------------------------------------------
// fp16 GEMM: C[M,N] = A[M,K] @ B[K,N]; tile 64x128, BK=32, 8 warps.
// EPI=false: q rows scaled by log2(e)/8 (exp2-domain softmax downstream).
// ---------------------------------------------------------------------------
template<bool EPI>
__global__ __launch_bounds__(256) void gemm_h(
    const __half* __restrict__ A, const __half* __restrict__ B,
    void* __restrict__ Cout, int M, int N, int K,
    const float* __restrict__ bias, const float* __restrict__ resid)
{
    extern __shared__ __half gsm[];
    __half* As = gsm;                  // 2 x [64][56]
    __half* Bs = gsm + 2 * 64 * 56;    // 2 x [32][136]

    const int tid = threadIdx.x, lane = tid & 31, wid = tid >> 5;
    const int g = lane >> 2, tg = lane & 3;
    const int wm = wid >> 2, wn = wid & 3;
    const int m0 = blockIdx.y * 64, n0 = blockIdx.x * 128;
    const int ar = tid >> 2, acq = (tid & 3) * 8;
    const int br = tid >> 4, bcq = (tid & 15) * 8;
    float acc[2][4][4] = {};

    auto issue = [&](int k0, int buf) {
        __half* Ad = As + buf * 64 * 56;
        __half* Bd = Bs + buf * 32 * 136;
        cpa16(saddr(&Ad[ar * 56 + acq]), &A[(size_t)(m0 + ar) * K + k0 + acq]);
        cpa16(saddr(&Bd[br * 136 + bcq]), &B[(size_t)(k0 + br) * N + n0 + bcq]);
        cpa16(saddr(&Bd[(br + 16) * 136 + bcq]), &B[(size_t)(k0 + br + 16) * N + n0 + bcq]);
    };

    issue(0, 0);
    CP_COMMIT();
    const int NKI = K / 32;
    for (int i = 0; i < NKI; i++) {
        if (i + 1 < NKI) { issue(32 * (i + 1), (i + 1) & 1); CP_COMMIT(); CP_WAIT1(); }
        else             { CP_WAIT0(); }
        __syncthreads();
        const __half* Ab = As + (i & 1) * 64 * 56;
        const __half* Bb = Bs + (i & 1) * 32 * 136;
        #pragma unroll
        for (int ks = 0; ks < 2; ks++) {
            const int k0 = ks * 16;
            unsigned af[2][4];
            #pragma unroll
            for (int mt = 0; mt < 2; mt++)
                ldm4(af[mt], saddr(&Ab[(wm * 32 + mt * 16 + (lane & 15)) * 56
                                        + k0 + (lane >> 4) * 8]));
            unsigned bf[2][4];
            #pragma unroll
            for (int np = 0; np < 2; np++)
                ldm4t(bf[np], saddr(&Bb[(k0 + (lane & 15)) * 136
                                         + wn * 32 + np * 16 + ((lane & 16) >> 1)]));
            #pragma unroll
            for (int mt = 0; mt < 2; mt++)
                #pragma unroll
                for (int np = 0; np < 2; np++) {
                    mma16(acc[mt][np * 2],     af[mt], bf[np][0], bf[np][1]);
                    mma16(acc[mt][np * 2 + 1], af[mt], bf[np][2], bf[np][3]);
                }
        }
        __syncthreads();
    }

    #pragma unroll
    for (int mt = 0; mt < 2; mt++) {
        int mA = m0 + wm * 32 + mt * 16 + g;
        int mB = mA + 8;
        if (EPI) {
            float* C = (float*)Cout;
            float biA = bias[mA], biB = bias[mB];
            #pragma unroll
            for (int nt = 0; nt < 4; nt++) {
                int n = n0 + wn * 32 + nt * 8 + 2 * tg;
                C[(size_t)mA * N + n]     = acc[mt][nt][0] + biA + resid[(size_t)mA * N + n];
                C[(size_t)mA * N + n + 1] = acc[mt][nt][1] + biA + resid[(size_t)mA * N + n + 1];
                C[(size_t)mB * N + n]     = acc[mt][nt][2] + biB + resid[(size_t)mB * N + n];
                C[(size_t)mB * N + n + 1] = acc[mt][nt][3] + biB + resid[(size_t)mB * N + n + 1];
            }
        } else {
            __half* C = (__half*)Cout;
            // q rows: fold softmax 1/8 scale AND log2(e) for exp2-domain scores
            float sc = ((mA / 64) % 3 == 0) ? 0.125f * 1.4426950408889634f : 1.0f;
            #pragma unroll
            for (int nt = 0; nt < 4; nt++) {
                int n = n0 + wn * 32 + nt * 8 + 2 * tg;
                C[(size_t)mA * N + n]     = __float2half(acc[mt][nt][0] * sc);
                C[(size_t)mA * N + n + 1] = __float2half(acc[mt][nt][1] * sc);
                C[(size_t)mB * N + n]     = __float2half(acc[mt][nt][2] * sc);
                C[(size_t)mB * N + n + 1] = __float2half(acc[mt][nt][3] * sc);
            }
        }
    }
}

// ---------------------------------------------------------------------------
// Flash attention, SPLIT-KV x4, fixed-base softmax (ex2.f16x2), l via
// ones-mma. 128-query tile, 4 warps x 32 rows. Key tile processed in TWO
// 32-key halves (S-half -> pack -> PV-half) to halve live sacc/pa registers
// and enable 3 CTAs/SM. Accumulation order identical to the full-tile form.
// ---------------------------------------------------------------------------
__global__ void __launch_bounds__(128, 3) attn_h(
    const __half* __restrict__ qkv)
{
    extern __shared__ __half sm[];
    __half* Qs  = sm;                   // [64][136]  (Q[d][t], t = 128 wide)
    __half* Ksb = sm + 64 * 136;        // 2 x [64][72]
    __half* Vsb = Ksb + 2 * 64 * 72;    // 2 x [64][72]

    const int hd = blockIdx.y, t0 = blockIdx.x * TQ;
    const int split = blockIdx.z;
    const int kbase = split * KEYS_PER_SPLIT;
    const __half* qp = qkv + (size_t)(hd * 192) * NTOK;
    const __half* kp = qp + (size_t)64 * NTOK;
    const __half* vp = kp + (size_t)64 * NTOK;

    const int tid = threadIdx.x, lane = tid & 31, wid = tid >> 5;
    const int g = lane >> 2, tg = lane & 3;
    const unsigned ONES2 = 0x3C003C00u;   // (1.0h, 1.0h)

    // stage Q (128 tokens x 64 d), pitch 136
    for (int i = tid; i < 1024; i += 128) {
        int c = i >> 4, t8 = (i & 15) * 8;
        cpa16(saddr(&Qs[c * 136 + t8]), &qp[(size_t)c * NTOK + t0 + t8]);
    }
    CP_COMMIT();
    for (int i = tid; i < 512; i += 128) {
        int c = i >> 3, s8 = (i & 7) * 8;
        cpa16(saddr(&Ksb[c * 72 + s8]), &kp[(size_t)c * NTOK + kbase + s8]);
        cpa16(saddr(&Vsb[c * 72 + s8]), &vp[(size_t)c * NTOK + kbase + s8]);
    }
    CP_COMMIT();
    CP_WAIT1();            // Q resident
    __syncthreads();

    // Q A-fragments for 2 m-tiles (trans from [d][t]), 4 k16 steps over d
    unsigned qa[2][4][4];
    {
        const int krow = (lane & 7) + ((lane & 16) >> 1);
        #pragma unroll
        for (int mt = 0; mt < 2; mt++) {
            const int mcol = wid * 32 + mt * 16 + (lane & 8);
            #pragma unroll
            for (int ks = 0; ks < 4; ks++)
                ldm4t(qa[mt][ks], saddr(&Qs[(ks * 16 + krow) * 136 + mcol]));
        }
    }

    float oacc[2][8][4] = {};
    float lacc[2][4] = {};     // l-row sums via ones-mma

    for (int it = 0; it < ITERS; it++) {
        if (it < ITERS - 1) {
            const int s0 = kbase + (it + 1) * 64, buf = (it + 1) & 1;
            __half* Kd = Ksb + buf * 64 * 72;
            __half* Vd = Vsb + buf * 64 * 72;
            for (int i = tid; i < 512; i += 128) {
                int c = i >> 3, s8 = (i & 7) * 8;
                cpa16(saddr(&Kd[c * 72 + s8]), &kp[(size_t)c * NTOK + s0 + s8]);
                cpa16(saddr(&Vd[c * 72 + s8]), &vp[(size_t)c * NTOK + s0 + s8]);
            }
            CP_COMMIT();
            CP_WAIT1();
        } else {
            CP_WAIT0();
        }
        __syncthreads();
        const __half* Ks = Ksb + (it & 1) * 64 * 72;
        const __half* Vs = Vsb + (it & 1) * 64 * 72;

        // process key tile in two 32-key halves
        #pragma unroll
        for (int h = 0; h < 2; h++) {
            // S-half: keys [h*32, h*32+32)
            float sacc[2][4][4] = {};
            #pragma unroll
            for (int ks = 0; ks < 4; ks++) {          // d-steps
                #pragma unroll
                for (int npl = 0; npl < 2; npl++) {
                    const int np = 2 * h + npl;
                    unsigned bf[4];
                    ldm4t(bf, saddr(&Ks[(ks * 16 + (lane & 15)) * 72
                                         + np * 16 + ((lane & 16) >> 1)]));
                    mma16(sacc[0][npl * 2],     qa[0][ks], bf[0], bf[1]);
                    mma16(sacc[0][npl * 2 + 1], qa[0][ks], bf[2], bf[3]);
                    mma16(sacc[1][npl * 2],     qa[1][ks], bf[0], bf[1]);
                    mma16(sacc[1][npl * 2 + 1], qa[1][ks], bf[2], bf[3]);
                }
            }

            // pack + ex2 (fp16 domain) + l via ones-mma
            unsigned pa[2][2][4];
            #pragma unroll
            for (int mt = 0; mt < 2; mt++) {
                #pragma unroll
                for (int j = 0; j < 2; j++) {
                    pa[mt][j][0] = ex2h2(h2u(__floats2half2_rn(sacc[mt][2 * j][0],     sacc[mt][2 * j][1])));
                    pa[mt][j][1] = ex2h2(h2u(__floats2half2_rn(sacc[mt][2 * j][2],     sacc[mt][2 * j][3])));
                    pa[mt][j][2] = ex2h2(h2u(__floats2half2_rn(sacc[mt][2 * j + 1][0], sacc[mt][2 * j + 1][1])));
                    pa[mt][j][3] = ex2h2(h2u(__floats2half2_rn(sacc[mt][2 * j + 1][2], sacc[mt][2 * j + 1][3])));
                    mma16(lacc[mt], pa[mt][j], ONES2, ONES2);
                }
            }

            // PV-half: key-steps ksp = 2h+j
            #pragma unroll
            for (int j = 0; j < 2; j++) {
                const int ksp = 2 * h + j;
                #pragma unroll
                for (int dp = 0; dp < 4; dp++) {
                    unsigned bf[4];
                    ldm4(bf, saddr(&Vs[(dp * 16 + (lane & 7) + ((lane & 16) >> 1)) * 72
                                        + ksp * 16 + (lane & 8)]));
                    mma16(oacc[0][dp * 2],     pa[0][j], bf[0], bf[1]);
                    mma16(oacc[0][dp * 2 + 1], pa[0][j], bf[2], bf[3]);
                    mma16(oacc[1][dp * 2],     pa[1][j], bf[0], bf[1]);
                    mma16(oacc[1][dp * 2 + 1], pa[1][j], bf[2], bf[3]);
                }
            }
        }
        __syncthreads();
    }

    // lacc[mt][0] = full row sum (row g), lacc[mt][2] = row g+8
    __half* op = g_oparth + (size_t)split * CDIM * NTOK;
    #pragma unroll
    for (int mt = 0; mt < 2; mt++) {
        #pragma unroll
        for (int n = 0; n < 8; n++) {
            int c = hd * 64 + n * 8 + 2 * tg;
            size_t base = (size_t)c * NTOK + t0 + wid * 32 + mt * 16 + g;
            op[base]            = __float2half(oacc[mt][n][0]);
            op[base + NTOK]     = __float2half(oacc[mt][n][1]);
            op[base + 8]        = __float2half(oacc[mt][n][2]);
            op[base + NTOK + 8] = __float2half(oacc[mt][n][3]);
        }
    }
    if (tg == 0) {
        float* lp = g_l + (size_t)(split * 4 + hd) * NTOK + t0 + wid * 32;
        lp[g]          = lacc[0][0];
        lp[g + 8]      = lacc[0][2];
        lp[16 + g]     = lacc[1][0];
        lp[16 + g + 8] = lacc[1][2];
    }
}

// ---------------------------------------------------------------------------
// linv: 1 / sum_s l_s per (head, token)
// ---------------------------------------------------------------------------
__global__ __launch_bounds__(256) void attn_linv()
{
    int idx = blockIdx.x * 256 + threadIdx.x;     // 0 .. 4*NTOK-1
    if (idx >= 4 * NTOK) return;
    float s = 0.f;
    #pragma unroll
    for (int sp = 0; sp < NSPLIT; sp++) s += g_l[(size_t)sp * 4 * NTOK + idx];
    g_linv[idx] = 1.f / s;
}

// ---------------------------------------------------------------------------
// Combine: h[c][t] = (sum_s O_s[c][t]) * linv[head][t]. Block = one channel;
// linv slice cached in SMEM.
// ---------------------------------------------------------------------------
__global__ __launch_bounds__(256) void attn_combine(__half* __restrict__ h)
{
    __shared__ float slinv[NTOK];
    const int c = blockIdx.x;
    const int head = c >> 6;
    for (int i = threadIdx.x; i < NTOK / 4; i += 256)
        reinterpret_cast<float4*>(slinv)[i] =
            reinterpret_cast<const float4*>(g_linv + (size_t)head * NTOK)[i];
    __syncthreads();

    for (int i = threadIdx.x; i < NTOK / 8; i += 256) {
        const int t8 = i * 8;
        float acc[8] = {};
        #pragma unroll
        for (int sp = 0; sp < NSPLIT; sp++) {
            uint4 v = *reinterpret_cast<const uint4*>(
                &g_oparth[(size_t)sp * CDIM * NTOK + (size_t)c * NTOK + t8]);
            const unsigned w[4] = {v.x, v.y, v.z, v.w};
            #pragma unroll
            for (int j = 0; j < 4; j++) {
                float2 f = __half22float2(*reinterpret_cast<const __half2*>(&w[j]));
                acc[2 * j]     += f.x;
                acc[2 * j + 1] += f.y;
            }
        }
        uint4 o;
        o.x = h2u(__floats2half2_rn(acc[0] * slinv[t8],     acc[1] * slinv[t8 + 1]));
        o.y = h2u(__floats2half2_rn(acc[2] * slinv[t8 + 2], acc[3] * slinv[t8 + 3]));
        o.z = h2u(__floats2half2_rn(acc[4] * slinv[t8 + 4], acc[5] * slinv[t8 + 5]));
        o.w = h2u(__floats2half2_rn(acc[6] * slinv[t8 + 6], acc[7] * slinv[t8 + 7]));
        *reinterpret_cast<uint4*>(h + (size_t)c * NTOK + t8) = o;
    }
}

// ---------------------------------------------------------------------------
extern "C" void kernel_launch(void* const* d_in, const int* in_sizes, int n_in,
                              void* d_out, int out_size)
{
    const float* x      = (const float*)d_in[0];
    const float* gamma  = (const float*)d_in[1];
    const float* beta   = (const float*)d_in[2];
    const float* w_qkv  = (const float*)d_in[3];
    const float* w_proj = (const float*)d_in[4];
    const float* b_proj = (const float*)d_in[5];
    float* out = (float*)d_out;

    __half *xn, *qkv, *h, *wq, *wp;
    cudaGetSymbolAddress((void**)&xn,  g_xn);
    cudaGetSymbolAddress((void**)&qkv, g_qkv);
    cudaGetSymbolAddress((void**)&h,   g_h);
    cudaGetSymbolAddress((void**)&wq,  g_wq);
    cudaGetSymbolAddress((void**)&wp,  g_wp);

    cudaFuncSetAttribute(attn_h, cudaFuncAttributeMaxDynamicSharedMemorySize, ATT_SMEM);
    cudaFuncSetAttribute(gemm_h<false>, cudaFuncAttributeMaxDynamicSharedMemorySize, GEMM_SMEM);
    cudaFuncSetAttribute(gemm_h<true>,  cudaFuncAttributeMaxDynamicSharedMemorySize, GEMM_SMEM);

    gn_stats_cvt<<<256, 256>>>(x, w_qkv, w_proj, wq, wp);
    gn_apply<<<512, 256>>>(x, gamma, beta, xn);
    gemm_h<false><<<dim3(NTOK / 128, 768 / 64), 256, GEMM_SMEM>>>(
        wq, xn, qkv, 768, NTOK, CDIM, nullptr, nullptr);
    attn_h<<<dim3(NTOK / TQ, 4, NSPLIT), 128, ATT_SMEM>>>(qkv);
    attn_linv<<<(4 * NTOK + 255) / 256, 256>>>();
    attn_combine<<<CDIM, 256>>>(h);
    gemm_h<true><<<dim3(NTOK / 128, CDIM / 64), 256, GEMM_SMEM>>>(
        wp, h, out, CDIM, NTOK, CDIM, b_proj, x);
}

// round 17
// speedup vs baseline: 1.5093x; 1.5093x over previous
#include <cuda_runtime.h>
#include <cuda_fp16.h>

namespace {
constexpr int NTOK = 4096;
constexpr int CDIM = 256;
constexpr int NSPLIT = 4;
constexpr int KEYS_PER_SPLIT = NTOK / NSPLIT;               // 1024
constexpr int ITERS = KEYS_PER_SPLIT / 64;                  // 16
constexpr int TQ = 128;                                     // queries per block
constexpr int ATT_SMEM  = (64 * 136 + 4 * 64 * 72) * 2;     // Q + 2K + 2V = 54272 B
constexpr int GEMM_SMEM = (2 * 64 * 56 + 2 * 32 * 136) * 2; // 31744 B
}

// Scratch (allocation-free rule: __device__ globals)
__device__ __half g_xn[CDIM * NTOK];
__device__ __half g_qkv[3 * CDIM * NTOK];
__device__ __half g_h[CDIM * NTOK];
__device__ __half g_wq[3 * CDIM * CDIM];
__device__ __half g_wp[CDIM * CDIM];
__device__ float2 g_part[128];
__device__ __half g_oparth[NSPLIT * CDIM * NTOK];  // fp16 partial O (unnormalized)
__device__ float  g_l[NSPLIT * 4 * NTOK];          // per (split, head, token) l-sum
__device__ float  g_linv[4 * NTOK];                // 1 / sum_s l_s per (head, token)

__device__ __forceinline__ unsigned saddr(const void* p) {
    return (unsigned)__cvta_generic_to_shared(p);
}
__device__ __forceinline__ void cpa16(unsigned dst, const void* src) {
    asm volatile("cp.async.cg.shared.global [%0], [%1], 16;\n" :: "r"(dst), "l"(src));
}
#define CP_COMMIT() asm volatile("cp.async.commit_group;\n" ::)
#define CP_WAIT0()  asm volatile("cp.async.wait_group 0;\n" ::)
#define CP_WAIT1()  asm volatile("cp.async.wait_group 1;\n" ::)

__device__ __forceinline__ unsigned h2u(__half2 h) {
    return *reinterpret_cast<unsigned*>(&h);
}
__device__ __forceinline__ unsigned ex2h2(unsigned x) {
    unsigned y;
    asm("ex2.approx.f16x2 %0, %1;" : "=r"(y) : "r"(x));
    return y;
}
__device__ __forceinline__ void mma16(float* c, const unsigned* a, unsigned b0, unsigned b1) {
    asm volatile(
        "mma.sync.aligned.m16n8k16.row.col.f32.f16.f16.f32 "
        "{%0,%1,%2,%3},{%4,%5,%6,%7},{%8,%9},{%0,%1,%2,%3};\n"
        : "+f"(c[0]), "+f"(c[1]), "+f"(c[2]), "+f"(c[3])
        : "r"(a[0]), "r"(a[1]), "r"(a[2]), "r"(a[3]), "r"(b0), "r"(b1));
}
__device__ __forceinline__ void ldm4(unsigned* r, unsigned a) {
    asm volatile("ldmatrix.sync.aligned.m8n8.x4.shared.b16 {%0,%1,%2,%3}, [%4];\n"
        : "=r"(r[0]), "=r"(r[1]), "=r"(r[2]), "=r"(r[3]) : "r"(a));
}
__device__ __forceinline__ void ldm4t(unsigned* r, unsigned a) {
    asm volatile("ldmatrix.sync.aligned.m8n8.x4.trans.shared.b16 {%0,%1,%2,%3}, [%4];\n"
        : "=r"(r[0]), "=r"(r[1]), "=r"(r[2]), "=r"(r[3]) : "r"(a));
}

// ---------------------------------------------------------------------------
// Fused: GN partial sums (blocks 0..127) + weight fp32->fp16 cvt (128..255)
// ---------------------------------------------------------------------------
__global__ __launch_bounds__(256) void gn_stats_cvt(
    const float* __restrict__ x,
    const float* __restrict__ wq, const float* __restrict__ wp,
    __half* __restrict__ dq, __half* __restrict__ dp)
{
    if (blockIdx.x < 128) {
        const int b = blockIdx.x;               // g*8 + slice
        const float4* xg = reinterpret_cast<const float4*>(x) + (size_t)b * 2048;
        float s = 0.f, s2 = 0.f;
        for (int i = threadIdx.x; i < 2048; i += 256) {
            float4 v = xg[i];
            s  += v.x + v.y + v.z + v.w;
            s2 += v.x * v.x + v.y * v.y + v.z * v.z + v.w * v.w;
        }
        #pragma unroll
        for (int o = 16; o; o >>= 1) {
            s  += __shfl_xor_sync(0xffffffffu, s, o);
            s2 += __shfl_xor_sync(0xffffffffu, s2, o);
        }
        __shared__ float r1[8], r2[8];
        if ((threadIdx.x & 31) == 0) { r1[threadIdx.x >> 5] = s; r2[threadIdx.x >> 5] = s2; }
        __syncthreads();
        if (threadIdx.x == 0) {
            float ts = 0.f, ts2 = 0.f;
            #pragma unroll
            for (int i = 0; i < 8; i++) { ts += r1[i]; ts2 += r2[i]; }
            g_part[b] = make_float2(ts, ts2);
        }
    } else {
        const int n1 = 3 * CDIM * CDIM / 2;
        const int nt = n1 + CDIM * CDIM / 2;
        for (int i = (blockIdx.x - 128) * 256 + threadIdx.x; i < nt; i += 128 * 256) {
            if (i < n1) {
                float2 v = reinterpret_cast<const float2*>(wq)[i];
                reinterpret_cast<__half2*>(dq)[i] = __floats2half2_rn(v.x, v.y);
            } else {
                float2 v = reinterpret_cast<const float2*>(wp)[i - n1];
                reinterpret_cast<__half2*>(dp)[i - n1] = __floats2half2_rn(v.x, v.y);
            }
        }
    }
}

// ---------------------------------------------------------------------------
// GroupNorm apply with inline per-channel scale computation, write fp16
// ---------------------------------------------------------------------------
__global__ __launch_bounds__(256) void gn_apply(
    const float* __restrict__ x, const float* __restrict__ gamma,
    const float* __restrict__ beta, __half* __restrict__ xn)
{
    __shared__ float2 sgab[CDIM];
    {
        const int c = threadIdx.x;
        const int g = c >> 4;
        float ts = 0.f, ts2 = 0.f;
        #pragma unroll
        for (int j = 0; j < 8; j++) { float2 p = g_part[g * 8 + j]; ts += p.x; ts2 += p.y; }
        const float inv = 1.f / 65536.f;
        float mu = ts * inv;
        float rstd = rsqrtf(ts2 * inv - mu * mu + 1e-5f);
        float ga = gamma[c] * rstd;
        sgab[c] = make_float2(ga, beta[c] - mu * ga);
    }
    __syncthreads();
    for (int i = blockIdx.x * 256 + threadIdx.x; i < 262144; i += gridDim.x * 256) {
        float2 gb = sgab[i >> 10];
        float4 v = reinterpret_cast<const float4*>(x)[i];
        uint2 o;
        o.x = h2u(__floats2half2_rn(v.x * gb.x + gb.y, v.y * gb.x + gb.y));
        o.y = h2u(__floats2half2_rn(v.z * gb.x + gb.y, v.w * gb.x + gb.y));
        reinterpret_cast<uint2*>(xn)[i] = o;
    }
}

// ---------------------------------------------------------------------------
// fp16 GEMM: C[M,N] = A[M,K] @ B[K,N]; tile 64x128, BK=32, 8 warps.
// EPI=false: q rows scaled by log2(e)/8 (exp2-domain softmax downstream).
// ---------------------------------------------------------------------------
template<bool EPI>
__global__ __launch_bounds__(256) void gemm_h(
    const __half* __restrict__ A, const __half* __restrict__ B,
    void* __restrict__ Cout, int M, int N, int K,
    const float* __restrict__ bias, const float* __restrict__ resid)
{
    extern __shared__ __half gsm[];
    __half* As = gsm;                  // 2 x [64][56]
    __half* Bs = gsm + 2 * 64 * 56;    // 2 x [32][136]

    const int tid = threadIdx.x, lane = tid & 31, wid = tid >> 5;
    const int g = lane >> 2, tg = lane & 3;
    const int wm = wid >> 2, wn = wid & 3;
    const int m0 = blockIdx.y * 64, n0 = blockIdx.x * 128;
    const int ar = tid >> 2, acq = (tid & 3) * 8;
    const int br = tid >> 4, bcq = (tid & 15) * 8;
    float acc[2][4][4] = {};

    auto issue = [&](int k0, int buf) {
        __half* Ad = As + buf * 64 * 56;
        __half* Bd = Bs + buf * 32 * 136;
        cpa16(saddr(&Ad[ar * 56 + acq]), &A[(size_t)(m0 + ar) * K + k0 + acq]);
        cpa16(saddr(&Bd[br * 136 + bcq]), &B[(size_t)(k0 + br) * N + n0 + bcq]);
        cpa16(saddr(&Bd[(br + 16) * 136 + bcq]), &B[(size_t)(k0 + br + 16) * N + n0 + bcq]);
    };

    issue(0, 0);
    CP_COMMIT();
    const int NKI = K / 32;
    for (int i = 0; i < NKI; i++) {
        if (i + 1 < NKI) { issue(32 * (i + 1), (i + 1) & 1); CP_COMMIT(); CP_WAIT1(); }
        else             { CP_WAIT0(); }
        __syncthreads();
        const __half* Ab = As + (i & 1) * 64 * 56;
        const __half* Bb = Bs + (i & 1) * 32 * 136;
        #pragma unroll
        for (int ks = 0; ks < 2; ks++) {
            const int k0 = ks * 16;
            unsigned af[2][4];
            #pragma unroll
            for (int mt = 0; mt < 2; mt++)
                ldm4(af[mt], saddr(&Ab[(wm * 32 + mt * 16 + (lane & 15)) * 56
                                        + k0 + (lane >> 4) * 8]));
            unsigned bf[2][4];
            #pragma unroll
            for (int np = 0; np < 2; np++)
                ldm4t(bf[np], saddr(&Bb[(k0 + (lane & 15)) * 136
                                         + wn * 32 + np * 16 + ((lane & 16) >> 1)]));
            #pragma unroll
            for (int mt = 0; mt < 2; mt++)
                #pragma unroll
                for (int np = 0; np < 2; np++) {
                    mma16(acc[mt][np * 2],     af[mt], bf[np][0], bf[np][1]);
                    mma16(acc[mt][np * 2 + 1], af[mt], bf[np][2], bf[np][3]);
                }
        }
        __syncthreads();
    }

    #pragma unroll
    for (int mt = 0; mt < 2; mt++) {
        int mA = m0 + wm * 32 + mt * 16 + g;
        int mB = mA + 8;
        if (EPI) {
            float* C = (float*)Cout;
            float biA = bias[mA], biB = bias[mB];
            #pragma unroll
            for (int nt = 0; nt < 4; nt++) {
                int n = n0 + wn * 32 + nt * 8 + 2 * tg;
                C[(size_t)mA * N + n]     = acc[mt][nt][0] + biA + resid[(size_t)mA * N + n];
                C[(size_t)mA * N + n + 1] = acc[mt][nt][1] + biA + resid[(size_t)mA * N + n + 1];
                C[(size_t)mB * N + n]     = acc[mt][nt][2] + biB + resid[(size_t)mB * N + n];
                C[(size_t)mB * N + n + 1] = acc[mt][nt][3] + biB + resid[(size_t)mB * N + n + 1];
            }
        } else {
            __half* C = (__half*)Cout;
            // q rows: fold softmax 1/8 scale AND log2(e) for exp2-domain scores
            float sc = ((mA / 64) % 3 == 0) ? 0.125f * 1.4426950408889634f : 1.0f;
            #pragma unroll
            for (int nt = 0; nt < 4; nt++) {
                int n = n0 + wn * 32 + nt * 8 + 2 * tg;
                C[(size_t)mA * N + n]     = __float2half(acc[mt][nt][0] * sc);
                C[(size_t)mA * N + n + 1] = __float2half(acc[mt][nt][1] * sc);
                C[(size_t)mB * N + n]     = __float2half(acc[mt][nt][2] * sc);
                C[(size_t)mB * N + n + 1] = __float2half(acc[mt][nt][3] * sc);
            }
        }
    }
}

// ---------------------------------------------------------------------------
// Flash attention, SPLIT-KV x4, fixed-base softmax (ex2.f16x2), l via
// ones-mma. 128-query tile, 4 warps x 32 rows. Key tile processed in TWO
// 32-key halves (S-half -> pack -> PV-half): halves are independent chains,
// giving intra-warp ILP. (128,2): spill-free (R16's (128,3) clamped to 168
// regs and spilled the accumulators -> 79us; this reverts that).
// ---------------------------------------------------------------------------
__global__ void __launch_bounds__(128, 2) attn_h(
    const __half* __restrict__ qkv)
{
    extern __shared__ __half sm[];
    __half* Qs  = sm;                   // [64][136]  (Q[d][t], t = 128 wide)
    __half* Ksb = sm + 64 * 136;        // 2 x [64][72]
    __half* Vsb = Ksb + 2 * 64 * 72;    // 2 x [64][72]

    const int hd = blockIdx.y, t0 = blockIdx.x * TQ;
    const int split = blockIdx.z;
    const int kbase = split * KEYS_PER_SPLIT;
    const __half* qp = qkv + (size_t)(hd * 192) * NTOK;
    const __half* kp = qp + (size_t)64 * NTOK;
    const __half* vp = kp + (size_t)64 * NTOK;

    const int tid = threadIdx.x, lane = tid & 31, wid = tid >> 5;
    const int g = lane >> 2, tg = lane & 3;
    const unsigned ONES2 = 0x3C003C00u;   // (1.0h, 1.0h)

    // stage Q (128 tokens x 64 d), pitch 136
    for (int i = tid; i < 1024; i += 128) {
        int c = i >> 4, t8 = (i & 15) * 8;
        cpa16(saddr(&Qs[c * 136 + t8]), &qp[(size_t)c * NTOK + t0 + t8]);
    }
    CP_COMMIT();
    for (int i = tid; i < 512; i += 128) {
        int c = i >> 3, s8 = (i & 7) * 8;
        cpa16(saddr(&Ksb[c * 72 + s8]), &kp[(size_t)c * NTOK + kbase + s8]);
        cpa16(saddr(&Vsb[c * 72 + s8]), &vp[(size_t)c * NTOK + kbase + s8]);
    }
    CP_COMMIT();
    CP_WAIT1();            // Q resident
    __syncthreads();

    // Q A-fragments for 2 m-tiles (trans from [d][t]), 4 k16 steps over d
    unsigned qa[2][4][4];
    {
        const int krow = (lane & 7) + ((lane & 16) >> 1);
        #pragma unroll
        for (int mt = 0; mt < 2; mt++) {
            const int mcol = wid * 32 + mt * 16 + (lane & 8);
            #pragma unroll
            for (int ks = 0; ks < 4; ks++)
                ldm4t(qa[mt][ks], saddr(&Qs[(ks * 16 + krow) * 136 + mcol]));
        }
    }

    float oacc[2][8][4] = {};
    float lacc[2][4] = {};     // l-row sums via ones-mma

    for (int it = 0; it < ITERS; it++) {
        if (it < ITERS - 1) {
            const int s0 = kbase + (it + 1) * 64, buf = (it + 1) & 1;
            __half* Kd = Ksb + buf * 64 * 72;
            __half* Vd = Vsb + buf * 64 * 72;
            for (int i = tid; i < 512; i += 128) {
                int c = i >> 3, s8 = (i & 7) * 8;
                cpa16(saddr(&Kd[c * 72 + s8]), &kp[(size_t)c * NTOK + s0 + s8]);
                cpa16(saddr(&Vd[c * 72 + s8]), &vp[(size_t)c * NTOK + s0 + s8]);
            }
            CP_COMMIT();
            CP_WAIT1();
        } else {
            CP_WAIT0();
        }
        __syncthreads();
        const __half* Ks = Ksb + (it & 1) * 64 * 72;
        const __half* Vs = Vsb + (it & 1) * 64 * 72;

        // process key tile in two 32-key halves (independent chains -> ILP)
        #pragma unroll
        for (int h = 0; h < 2; h++) {
            // S-half: keys [h*32, h*32+32)
            float sacc[2][4][4] = {};
            #pragma unroll
            for (int ks = 0; ks < 4; ks++) {          // d-steps
                #pragma unroll
                for (int npl = 0; npl < 2; npl++) {
                    const int np = 2 * h + npl;
                    unsigned bf[4];
                    ldm4t(bf, saddr(&Ks[(ks * 16 + (lane & 15)) * 72
                                         + np * 16 + ((lane & 16) >> 1)]));
                    mma16(sacc[0][npl * 2],     qa[0][ks], bf[0], bf[1]);
                    mma16(sacc[0][npl * 2 + 1], qa[0][ks], bf[2], bf[3]);
                    mma16(sacc[1][npl * 2],     qa[1][ks], bf[0], bf[1]);
                    mma16(sacc[1][npl * 2 + 1], qa[1][ks], bf[2], bf[3]);
                }
            }

            // pack + ex2 (fp16 domain) + l via ones-mma
            unsigned pa[2][2][4];
            #pragma unroll
            for (int mt = 0; mt < 2; mt++) {
                #pragma unroll
                for (int j = 0; j < 2; j++) {
                    pa[mt][j][0] = ex2h2(h2u(__floats2half2_rn(sacc[mt][2 * j][0],     sacc[mt][2 * j][1])));
                    pa[mt][j][1] = ex2h2(h2u(__floats2half2_rn(sacc[mt][2 * j][2],     sacc[mt][2 * j][3])));
                    pa[mt][j][2] = ex2h2(h2u(__floats2half2_rn(sacc[mt][2 * j + 1][0], sacc[mt][2 * j + 1][1])));
                    pa[mt][j][3] = ex2h2(h2u(__floats2half2_rn(sacc[mt][2 * j + 1][2], sacc[mt][2 * j + 1][3])));
                    mma16(lacc[mt], pa[mt][j], ONES2, ONES2);
                }
            }

            // PV-half: key-steps ksp = 2h+j
            #pragma unroll
            for (int j = 0; j < 2; j++) {
                const int ksp = 2 * h + j;
                #pragma unroll
                for (int dp = 0; dp < 4; dp++) {
                    unsigned bf[4];
                    ldm4(bf, saddr(&Vs[(dp * 16 + (lane & 7) + ((lane & 16) >> 1)) * 72
                                        + ksp * 16 + (lane & 8)]));
                    mma16(oacc[0][dp * 2],     pa[0][j], bf[0], bf[1]);
                    mma16(oacc[0][dp * 2 + 1], pa[0][j], bf[2], bf[3]);
                    mma16(oacc[1][dp * 2],     pa[1][j], bf[0], bf[1]);
                    mma16(oacc[1][dp * 2 + 1], pa[1][j], bf[2], bf[3]);
                }
            }
        }
        __syncthreads();
    }

    // lacc[mt][0] = full row sum (row g), lacc[mt][2] = row g+8
    __half* op = g_oparth + (size_t)split * CDIM * NTOK;
    #pragma unroll
    for (int mt = 0; mt < 2; mt++) {
        #pragma unroll
        for (int n = 0; n < 8; n++) {
            int c = hd * 64 + n * 8 + 2 * tg;
            size_t base = (size_t)c * NTOK + t0 + wid * 32 + mt * 16 + g;
            op[base]            = __float2half(oacc[mt][n][0]);
            op[base + NTOK]     = __float2half(oacc[mt][n][1]);
            op[base + 8]        = __float2half(oacc[mt][n][2]);
            op[base + NTOK + 8] = __float2half(oacc[mt][n][3]);
        }
    }
    if (tg == 0) {
        float* lp = g_l + (size_t)(split * 4 + hd) * NTOK + t0 + wid * 32;
        lp[g]          = lacc[0][0];
        lp[g + 8]      = lacc[0][2];
        lp[16 + g]     = lacc[1][0];
        lp[16 + g + 8] = lacc[1][2];
    }
}

// ---------------------------------------------------------------------------
// linv: 1 / sum_s l_s per (head, token)
// ---------------------------------------------------------------------------
__global__ __launch_bounds__(256) void attn_linv()
{
    int idx = blockIdx.x * 256 + threadIdx.x;     // 0 .. 4*NTOK-1
    if (idx >= 4 * NTOK) return;
    float s = 0.f;
    #pragma unroll
    for (int sp = 0; sp < NSPLIT; sp++) s += g_l[(size_t)sp * 4 * NTOK + idx];
    g_linv[idx] = 1.f / s;
}

// ---------------------------------------------------------------------------
// Combine: h[c][t] = (sum_s O_s[c][t]) * linv[head][t]. Block = one channel;
// linv slice cached in SMEM.
// ---------------------------------------------------------------------------
__global__ __launch_bounds__(256) void attn_combine(__half* __restrict__ h)
{
    __shared__ float slinv[NTOK];
    const int c = blockIdx.x;
    const int head = c >> 6;
    for (int i = threadIdx.x; i < NTOK / 4; i += 256)
        reinterpret_cast<float4*>(slinv)[i] =
            reinterpret_cast<const float4*>(g_linv + (size_t)head * NTOK)[i];
    __syncthreads();

    for (int i = threadIdx.x; i < NTOK / 8; i += 256) {
        const int t8 = i * 8;
        float acc[8] = {};
        #pragma unroll
        for (int sp = 0; sp < NSPLIT; sp++) {
            uint4 v = *reinterpret_cast<const uint4*>(
                &g_oparth[(size_t)sp * CDIM * NTOK + (size_t)c * NTOK + t8]);
            const unsigned w[4] = {v.x, v.y, v.z, v.w};
            #pragma unroll
            for (int j = 0; j < 4; j++) {
                float2 f = __half22float2(*reinterpret_cast<const __half2*>(&w[j]));
                acc[2 * j]     += f.x;
                acc[2 * j + 1] += f.y;
            }
        }
        uint4 o;
        o.x = h2u(__floats2half2_rn(acc[0] * slinv[t8],     acc[1] * slinv[t8 + 1]));
        o.y = h2u(__floats2half2_rn(acc[2] * slinv[t8 + 2], acc[3] * slinv[t8 + 3]));
        o.z = h2u(__floats2half2_rn(acc[4] * slinv[t8 + 4], acc[5] * slinv[t8 + 5]));
        o.w = h2u(__floats2half2_rn(acc[6] * slinv[t8 + 6], acc[7] * slinv[t8 + 7]));
        *reinterpret_cast<uint4*>(h + (size_t)c * NTOK + t8) = o;
    }
}

// ---------------------------------------------------------------------------
extern "C" void kernel_launch(void* const* d_in, const int* in_sizes, int n_in,
                              void* d_out, int out_size)
{
    const float* x      = (const float*)d_in[0];
    const float* gamma  = (const float*)d_in[1];
    const float* beta   = (const float*)d_in[2];
    const float* w_qkv  = (const float*)d_in[3];
    const float* w_proj = (const float*)d_in[4];
    const float* b_proj = (const float*)d_in[5];
    float* out = (float*)d_out;

    __half *xn, *qkv, *h, *wq, *wp;
    cudaGetSymbolAddress((void**)&xn,  g_xn);
    cudaGetSymbolAddress((void**)&qkv, g_qkv);
    cudaGetSymbolAddress((void**)&h,   g_h);
    cudaGetSymbolAddress((void**)&wq,  g_wq);
    cudaGetSymbolAddress((void**)&wp,  g_wp);

    cudaFuncSetAttribute(attn_h, cudaFuncAttributeMaxDynamicSharedMemorySize, ATT_SMEM);
    cudaFuncSetAttribute(gemm_h<false>, cudaFuncAttributeMaxDynamicSharedMemorySize, GEMM_SMEM);
    cudaFuncSetAttribute(gemm_h<true>,  cudaFuncAttributeMaxDynamicSharedMemorySize, GEMM_SMEM);

    gn_stats_cvt<<<256, 256>>>(x, w_qkv, w_proj, wq, wp);
    gn_apply<<<512, 256>>>(x, gamma, beta, xn);
    gemm_h<false><<<dim3(NTOK / 128, 768 / 64), 256, GEMM_SMEM>>>(
        wq, xn, qkv, 768, NTOK, CDIM, nullptr, nullptr);
    attn_h<<<dim3(NTOK / TQ, 4, NSPLIT), 128, ATT_SMEM>>>(qkv);
    attn_linv<<<(4 * NTOK + 255) / 256, 256>>>();
    attn_combine<<<CDIM, 256>>>(h);
    gemm_h<true><<<dim3(NTOK / 128, CDIM / 64), 256, GEMM_SMEM>>>(
        wp, h, out, CDIM, NTOK, CDIM, b_proj, x);
}